// round 10
// baseline (speedup 1.0000x reference)
#include <cuda_runtime.h>
#include <math.h>

#define B 16
#define H 1024
#define V 32000
#define T 11
#define G 4096
#define FCB (V/64)     // 500 tiles of 64 vocab rows
#define FCGRID 296     // persistent fc blocks (2 CTAs/SM x 148)

typedef unsigned long long ull;

// -------- scratch (static device globals: no allocation allowed) --------
__device__ float g_h[B*H];          // current hidden [b][k]
__device__ float g_gc[G*B];         // step-invariant gate bias: h0@W_hh.T + b_ih + b_hh, [row][b]
__device__ float g_pmax[FCB*B];     // per-tile argmax partial values (logits of last computed step)
__device__ int   g_pidx[FCB*B];     // per-tile argmax partial indices
__device__ int   g_hist[(T+1)*B];   // token history per step
__device__ int   g_src[T+1];        // first step with identical token vector (== t if unique)
__device__ int   g_ctr[T];          // per-step fc work-queue counters (reset by gconst each replay)

__device__ __forceinline__ float sigm(float x){ return 1.f/(1.f+expf(-x)); }

// Warp-cooperative GEMM, BW-optimized:
//  * STG-deep explicit LDG staging (back-to-back ld.global.nc.v2.u64 into regs
//    before any consumer) -> guaranteed MLP>=STG/warp. Round-5 ncu showed the
//    interleaved version ran at 330 GB/s (MLP<1, latency-serialized).
//  * single packed accumulator per batch (32 regs): both k-pair FFMA2s chain
//    into one acc; 16 interleaved b-chains give ILP.
// Warp computes 8 rows x 16 batches; K=1024 split 4-way across lanes; h reads
// are warp-broadcast LDS (8 lanes share each address -> conflict-free).
// Shfl-reduce over k-slices; afterwards all lanes hold all 16 batch dots.
template<int STG>
__device__ __forceinline__ void gemm_rows(const float* __restrict__ W, int row, int ksub,
                                          const float4* __restrict__ h4, float acc[B]) {
    const float4* w4 = reinterpret_cast<const float4*>(W) + (size_t)row*(H/4) + ksub;
    unsigned hbase = (unsigned)__cvta_generic_to_shared(h4) + ksub*16;
    ull a[B];
#pragma unroll
    for (int b=0;b<B;b++) a[b]=0ull;                  // (0.f,0.f) packed
#pragma unroll 1
    for (int jb=0;jb<H/16;jb+=STG){
        ull wxy[STG], wzw[STG];
#pragma unroll
        for (int s=0;s<STG;s++){
            asm("ld.global.nc.v2.u64 {%0,%1},[%2];"
                : "=l"(wxy[s]), "=l"(wzw[s]) : "l"(w4 + (jb+s)*4));
        }
#pragma unroll
        for (int s=0;s<STG;s++){
            unsigned ha = hbase + (jb+s)*64;
#pragma unroll
            for (int b=0;b<B;b++){
                ull hxy, hzw;
                asm("ld.shared.v2.u64 {%0,%1},[%2];"
                    : "=l"(hxy), "=l"(hzw) : "r"(ha + b*(H*4)));
                asm("fma.rn.f32x2 %0,%1,%2,%3;" : "=l"(a[b]) : "l"(wzw[s]), "l"(hzw), "l"(a[b]));
                asm("fma.rn.f32x2 %0,%1,%2,%3;" : "=l"(a[b]) : "l"(wxy[s]), "l"(hxy), "l"(a[b]));
            }
        }
    }
#pragma unroll
    for (int b=0;b<B;b++){
        float x0,y0;
        asm("mov.b64 {%0,%1},%2;" : "=f"(x0), "=f"(y0) : "l"(a[b]));
        acc[b] = x0+y0;
    }
#pragma unroll
    for (int b=0;b<B;b++){
        acc[b] += __shfl_xor_sync(0xffffffffu, acc[b], 1);
        acc[b] += __shfl_xor_sync(0xffffffffu, acc[b], 2);
    }
}

// -------- step-invariant gates + state/queue init  (64 blocks -> <=1 CTA/SM,
// registers free: use deep staging STG=16 for max MLP)
__global__ void __launch_bounds__(256) gconst_kernel(const float* __restrict__ h0,
    const float* __restrict__ Whh, const float* __restrict__ bih, const float* __restrict__ bhh){
    extern __shared__ float smem[];
    float4* h4 = (float4*)smem;
    int tid = threadIdx.x;
    const float4* hg = (const float4*)h0;
    for (int i=tid;i<B*H/4;i+=256) h4[i]=hg[i];
    if (blockIdx.x==0 && tid<B) g_hist[tid]=1;        // SOS token at step 0
    if (blockIdx.x==0 && tid==B) g_src[0]=0;
    if (blockIdx.x==0 && tid>=32 && tid<32+T) g_ctr[tid-32]=0;  // reset fc work queues
    __syncthreads();
    int warp=tid>>5, lane=tid&31, rs=lane>>2, ksub=lane&3;
    int row = blockIdx.x*64 + warp*8 + rs;
    float acc[B];
    gemm_rows<16>(Whh, row, ksub, h4, acc);
    float bb = bih[row]+bhh[row];
#pragma unroll
    for (int i=0;i<4;i++){ int b=ksub*4+i; g_gc[row*B+b]=acc[b]+bb; }
}

// -------- per-step LSTM with FUSED argmax finalize + memo bookkeeping.
// All 64 blocks redundantly reduce the 500-tile partials (valid for step t-1:
// partials always hold the last computed step's logits, bit-identical to t-1's
// even across memo-skipped steps), derive this step's tokens, maintain
// history/g_src (identical writes from all blocks are benign), then either run
// the gate GEMM or early-exit on dup steps.
__global__ void __launch_bounds__(256) lstm_kernel(const float* __restrict__ emb,
    const float* __restrict__ Wih, const float* __restrict__ c0, int t){
    extern __shared__ float smem[];
    float4* x4 = (float4*)smem;          // 16x1024 floats = 64KB
    float*  gs = smem + B*H;             // [4][16][16]
    __shared__ int toks[B];
    __shared__ int s_src;
    int tid = threadIdx.x;

    if (t==0){
        if (tid<B) toks[tid]=1;          // SOS
        if (tid==0) s_src=0;
    } else {
        // 16 threads per batch reduce 500 partials
        int b = tid>>4, r0 = tid&15;
        float bv=-3.4e38f; int bi=0x7fffffff;
        for (int i=r0;i<FCB;i+=16){
            float v=g_pmax[i*B+b]; int id=g_pidx[i*B+b];
            if (v>bv || (v==bv && id<bi)){bv=v;bi=id;}
        }
#pragma unroll
        for (int off=8;off;off>>=1){
            float ov=__shfl_xor_sync(0xffffffffu,bv,off,16);
            int   oi=__shfl_xor_sync(0xffffffffu,bi,off,16);
            if (ov>bv || (ov==bv && oi<bi)){bv=ov;bi=oi;}
        }
        if (r0==0) toks[b]=bi;
        __syncthreads();
        if (tid==0){
            int s = t;
            for (int tp=0;tp<t;tp++){
                bool eq=true;
                for (int b2=0;b2<B;b2++) eq = eq && (g_hist[tp*B+b2]==toks[b2]);
                if (eq){ s=tp; break; }
            }
            for (int b2=0;b2<B;b2++) g_hist[t*B+b2]=toks[b2];
            g_src[t]=s;                  // all blocks write identical value
            s_src=s;
        }
    }
    __syncthreads();
    if (s_src != t) return;              // dup step: h not needed (fc copies logits)

    // vectorized embed + relu into shared
    const float4* emb4 = (const float4*)emb;
    for (int i=tid;i<B*(H/4);i+=256){
        int b=i>>8, k4=i&255;
        float4 v = emb4[(size_t)toks[b]*(H/4) + k4];
        v.x=fmaxf(v.x,0.f); v.y=fmaxf(v.y,0.f); v.z=fmaxf(v.z,0.f); v.w=fmaxf(v.w,0.f);
        x4[i]=v;
    }
    __syncthreads();
    int warp=tid>>5, lane=tid&31, rs=lane>>2, ksub=lane&3;
    int g  = warp>>1;                    // gate 0..3 (i,f,g,o)
    int jj = (warp&1)*8 + rs;
    int j0 = blockIdx.x*16;
    int row = g*H + j0 + jj;
    float acc[B];
    gemm_rows<16>(Wih, row, ksub, x4, acc);   // 64 blocks -> deep staging free
#pragma unroll
    for (int i=0;i<4;i++){ int b=ksub*4+i; gs[(g*16+jj)*16+b] = acc[b] + g_gc[row*B+b]; }
    __syncthreads();
    int b=tid&15, j2=tid>>4;
    float iv=gs[(0*16+j2)*16+b], fv=gs[(1*16+j2)*16+b];
    float gv=gs[(2*16+j2)*16+b], ov=gs[(3*16+j2)*16+b];
    int j=j0+j2;
    float c = sigm(fv)*c0[b*H+j] + sigm(iv)*tanhf(gv);
    float h = sigm(ov)*tanhf(c);
    g_h[b*H+j]=h;
}

// -------- persistent per-step fc: 296 blocks pull 64-row tiles from an atomic
// queue (deadlock-free regardless of occupancy; near-perfect wave balance).
// ZIGZAG tile order: odd steps traverse fcW back-to-front so the ~100+MB of
// fcW left resident in the 126MB L2 by the previous step (L2 persists across
// launches; only L1D is flushed) is re-read as hits instead of thrashed.
// h loaded to shared ONCE per block. STG=8 keeps regs <=128 for 2 CTA/SM.
// On dup steps degrades to bit-exact copy.
__global__ void __launch_bounds__(256) fc_kernel(const float* __restrict__ fcW,
    const float* __restrict__ fcb, float* __restrict__ out, int t){
    extern __shared__ float smem[];
    float4* h4 = (float4*)smem;          // 64KB
    float*  lg = smem + B*H;             // [64][17] padded logits tile
    __shared__ int s_src;
    __shared__ int s_tile;
    int tid = threadIdx.x;
    if (tid==0) s_src=g_src[t];
    __syncthreads();

    if (s_src != t){
        int tp = s_src;
        for(;;){
            if (tid==0) s_tile = atomicAdd(&g_ctr[t],1);
            __syncthreads();
            int tile = s_tile;
            if (tile >= FCB) return;
            for (int i=tid;i<64*B;i+=256){
                int b=i>>6, vl=i&63;
                size_t col = (size_t)tile*64 + vl;
                out[(size_t)b*T*V + (size_t)t*V + col] =
                    out[(size_t)b*T*V + (size_t)tp*V + col];
            }
            __syncthreads();
        }
    }

    const float4* hg = (const float4*)g_h;
    for (int i=tid;i<B*H/4;i+=256) h4[i]=hg[i];
    __syncthreads();
    int warp=tid>>5, lane=tid&31, rs=lane>>2, ksub=lane&3;
    int rowLoc = warp*8 + rs;

    for(;;){
        if (tid==0) s_tile = atomicAdd(&g_ctr[t],1);
        __syncthreads();
        int n = s_tile;
        if (n >= FCB) return;
        int tile = (t & 1) ? (FCB-1-n) : n;   // zigzag across steps for L2 reuse
        int row = tile*64 + rowLoc;
        float acc[B];
        gemm_rows<8>(fcW, row, ksub, h4, acc);
        float bias = fcb[row];
#pragma unroll
        for (int i=0;i<4;i++){ int b=ksub*4+i; lg[rowLoc*17+b] = acc[b]+bias; }
        __syncthreads();
        for (int i=tid;i<64*B;i+=256){
            int b=i>>6, vl=i&63;
            out[(size_t)b*T*V + (size_t)t*V + tile*64 + vl] = lg[vl*17+b];
        }
        // tile-level argmax per batch, first-index tie-break
        int b = tid>>4, r0 = tid&15;
        float bv=-3.4e38f; int bi=0;
        for (int r=r0;r<64;r+=16){ float v=lg[r*17+b]; if (v>bv){bv=v;bi=r;} }
#pragma unroll
        for (int off=8;off;off>>=1){
            float ov=__shfl_xor_sync(0xffffffffu,bv,off,16);
            int   oi=__shfl_xor_sync(0xffffffffu,bi,off,16);
            if (ov>bv || (ov==bv && oi<bi)){bv=ov;bi=oi;}
        }
        if (r0==0){ g_pmax[tile*B+b]=bv; g_pidx[tile*B+b]=tile*64+bi; }
        __syncthreads();                  // lg reused next tile
    }
}

// -------- final in-place log_softmax over each of the 176 rows of length 32000
__global__ void __launch_bounds__(256) lsm_kernel(float* __restrict__ out){
    __shared__ float red[256];
    float* row = out + (size_t)blockIdx.x*V;
    int tid=threadIdx.x;
    float m=-3.4e38f;
    for (int i=tid;i<V;i+=256) m=fmaxf(m,row[i]);
    red[tid]=m; __syncthreads();
    for (int s=128;s;s>>=1){ if (tid<s) red[tid]=fmaxf(red[tid],red[tid+s]); __syncthreads(); }
    m=red[0]; __syncthreads();
    float sum=0.f;
    for (int i=tid;i<V;i+=256) sum+=expf(row[i]-m);
    red[tid]=sum; __syncthreads();
    for (int s=128;s;s>>=1){ if (tid<s) red[tid]+=red[tid+s]; __syncthreads(); }
    float lse=logf(red[0])+m;
    for (int i=tid;i<V;i+=256) row[i]=row[i]-lse;
}

extern "C" void kernel_launch(void* const* d_in, const int* in_sizes, int n_in,
                              void* d_out, int out_size){
    // metadata order: encoder_outputs, h0, c0, emb, W_ih, W_hh, b_ih, b_hh, fc_W, fc_b
    const float* h0 =(const float*)d_in[1];
    const float* c0 =(const float*)d_in[2];
    const float* emb=(const float*)d_in[3];
    const float* Wih=(const float*)d_in[4];
    const float* Whh=(const float*)d_in[5];
    const float* bih=(const float*)d_in[6];
    const float* bhh=(const float*)d_in[7];
    const float* fcW=(const float*)d_in[8];
    const float* fcb=(const float*)d_in[9];
    float* out=(float*)d_out;

    cudaFuncSetAttribute(fc_kernel,     cudaFuncAttributeMaxDynamicSharedMemorySize, (B*H + 64*17)*4);
    cudaFuncSetAttribute(lstm_kernel,   cudaFuncAttributeMaxDynamicSharedMemorySize, (B*H + 4*16*16)*4);
    cudaFuncSetAttribute(gconst_kernel, cudaFuncAttributeMaxDynamicSharedMemorySize, B*H*4);

    gconst_kernel<<<G/64,256,B*H*4>>>(h0,Whh,bih,bhh);
    for (int t=0;t<T;t++){
        lstm_kernel<<<H/16,256,(B*H + 4*16*16)*4>>>(emb,Wih,c0,t);
        fc_kernel<<<FCGRID,256,(B*H + 64*17)*4>>>(fcW,fcb,out,t);
    }
    lsm_kernel<<<B*T,256>>>(out);
}

// round 14
// speedup vs baseline: 1.5445x; 1.5445x over previous
#include <cuda_runtime.h>
#include <math.h>

#define B 16
#define H 1024
#define V 32000
#define T 11
#define G 4096
#define FCB (V/64)     // 500 tiles of 64 vocab rows
#define FCGRID 296     // persistent fc blocks (2 CTAs/SM x 148)

typedef unsigned long long ull;

// -------- scratch (static device globals: no allocation allowed) --------
__device__ float g_h[B*H];          // current hidden [b][k]
__device__ float g_gc[G*B];         // step-invariant gate bias: h0@W_hh.T + b_ih + b_hh, [row][b]
__device__ float g_pmax[FCB*B];     // per-tile argmax partial values (logits of last computed step)
__device__ int   g_pidx[FCB*B];     // per-tile argmax partial indices
__device__ int   g_hist[(T+1)*B];   // token history per step
__device__ int   g_src[T+1];        // first step with identical token vector (== t if unique)
__device__ int   g_ctr[T];          // per-step fc work-queue counters (reset by gconst each replay)

__device__ __forceinline__ float sigm(float x){ return 1.f/(1.f+expf(-x)); }

// Warp-cooperative GEMM, BW-optimized.
// ROUND-10 LESSON: staged loads were SUNK (lstm regs=78 — staging never
// materialized), rebuilding the latency-serialized pattern (309 GB/s).
// Two-level fix: (1) asm volatile pins the batched-load order in PTX;
// (2) __launch_bounds__ minBlocks hints give ptxas an explicit register
// budget (255 for lstm/gconst at 1 CTA/SM, 128 for fc at 2 CTA/SM) so it
// has no pressure motive to collapse the staging live ranges.
//  * single packed accumulator per batch (32 regs); 16 interleaved b-chains.
// Warp computes 8 rows x 16 batches; K=1024 split 4-way across lanes; h reads
// are warp-broadcast LDS (8 lanes share each address -> conflict-free).
// Shfl-reduce over k-slices; afterwards all lanes hold all 16 batch dots.
template<int STG>
__device__ __forceinline__ void gemm_rows(const float* __restrict__ W, int row, int ksub,
                                          const float4* __restrict__ h4, float acc[B]) {
    const float4* w4 = reinterpret_cast<const float4*>(W) + (size_t)row*(H/4) + ksub;
    unsigned hbase = (unsigned)__cvta_generic_to_shared(h4) + ksub*16;
    ull a[B];
#pragma unroll
    for (int b=0;b<B;b++) a[b]=0ull;                  // (0.f,0.f) packed
#pragma unroll 1
    for (int jb=0;jb<H/16;jb+=STG){
        ull wxy[STG], wzw[STG];
#pragma unroll
        for (int s=0;s<STG;s++){
            asm volatile("ld.global.nc.v2.u64 {%0,%1},[%2];"
                : "=l"(wxy[s]), "=l"(wzw[s]) : "l"(w4 + (jb+s)*4));
        }
#pragma unroll
        for (int s=0;s<STG;s++){
            unsigned ha = hbase + (jb+s)*64;
#pragma unroll
            for (int b=0;b<B;b++){
                ull hxy, hzw;
                asm("ld.shared.v2.u64 {%0,%1},[%2];"
                    : "=l"(hxy), "=l"(hzw) : "r"(ha + b*(H*4)));
                asm("fma.rn.f32x2 %0,%1,%2,%3;" : "=l"(a[b]) : "l"(wzw[s]), "l"(hzw), "l"(a[b]));
                asm("fma.rn.f32x2 %0,%1,%2,%3;" : "=l"(a[b]) : "l"(wxy[s]), "l"(hxy), "l"(a[b]));
            }
        }
    }
#pragma unroll
    for (int b=0;b<B;b++){
        float x0,y0;
        asm("mov.b64 {%0,%1},%2;" : "=f"(x0), "=f"(y0) : "l"(a[b]));
        acc[b] = x0+y0;
    }
#pragma unroll
    for (int b=0;b<B;b++){
        acc[b] += __shfl_xor_sync(0xffffffffu, acc[b], 1);
        acc[b] += __shfl_xor_sync(0xffffffffu, acc[b], 2);
    }
}

// -------- step-invariant gates + state/queue init  (64 blocks -> 1 CTA/SM is
// free: minBlocks=1 gives ptxas the full 255-reg budget for STG=16 staging)
__global__ void __launch_bounds__(256,1) gconst_kernel(const float* __restrict__ h0,
    const float* __restrict__ Whh, const float* __restrict__ bih, const float* __restrict__ bhh){
    extern __shared__ float smem[];
    float4* h4 = (float4*)smem;
    int tid = threadIdx.x;
    const float4* hg = (const float4*)h0;
    for (int i=tid;i<B*H/4;i+=256) h4[i]=hg[i];
    if (blockIdx.x==0 && tid<B) g_hist[tid]=1;        // SOS token at step 0
    if (blockIdx.x==0 && tid==B) g_src[0]=0;
    if (blockIdx.x==0 && tid>=32 && tid<32+T) g_ctr[tid-32]=0;  // reset fc work queues
    __syncthreads();
    int warp=tid>>5, lane=tid&31, rs=lane>>2, ksub=lane&3;
    int row = blockIdx.x*64 + warp*8 + rs;
    float acc[B];
    gemm_rows<16>(Whh, row, ksub, h4, acc);
    float bb = bih[row]+bhh[row];
#pragma unroll
    for (int i=0;i<4;i++){ int b=ksub*4+i; g_gc[row*B+b]=acc[b]+bb; }
}

// -------- per-step LSTM with FUSED argmax finalize + memo bookkeeping.
// All 64 blocks redundantly reduce the 500-tile partials (valid for step t-1:
// partials always hold the last computed step's logits, bit-identical to t-1's
// even across memo-skipped steps), derive this step's tokens, maintain
// history/g_src (identical writes from all blocks are benign), then either run
// the gate GEMM or early-exit on dup steps.
__global__ void __launch_bounds__(256,1) lstm_kernel(const float* __restrict__ emb,
    const float* __restrict__ Wih, const float* __restrict__ c0, int t){
    extern __shared__ float smem[];
    float4* x4 = (float4*)smem;          // 16x1024 floats = 64KB
    float*  gs = smem + B*H;             // [4][16][16]
    __shared__ int toks[B];
    __shared__ int s_src;
    int tid = threadIdx.x;

    if (t==0){
        if (tid<B) toks[tid]=1;          // SOS
        if (tid==0) s_src=0;
    } else {
        // 16 threads per batch reduce 500 partials
        int b = tid>>4, r0 = tid&15;
        float bv=-3.4e38f; int bi=0x7fffffff;
        for (int i=r0;i<FCB;i+=16){
            float v=g_pmax[i*B+b]; int id=g_pidx[i*B+b];
            if (v>bv || (v==bv && id<bi)){bv=v;bi=id;}
        }
#pragma unroll
        for (int off=8;off;off>>=1){
            float ov=__shfl_xor_sync(0xffffffffu,bv,off,16);
            int   oi=__shfl_xor_sync(0xffffffffu,bi,off,16);
            if (ov>bv || (ov==bv && oi<bi)){bv=ov;bi=oi;}
        }
        if (r0==0) toks[b]=bi;
        __syncthreads();
        if (tid==0){
            int s = t;
            for (int tp=0;tp<t;tp++){
                bool eq=true;
                for (int b2=0;b2<B;b2++) eq = eq && (g_hist[tp*B+b2]==toks[b2]);
                if (eq){ s=tp; break; }
            }
            for (int b2=0;b2<B;b2++) g_hist[t*B+b2]=toks[b2];
            g_src[t]=s;                  // all blocks write identical value
            s_src=s;
        }
    }
    __syncthreads();
    if (s_src != t) return;              // dup step: h not needed (fc copies logits)

    // vectorized embed + relu into shared
    const float4* emb4 = (const float4*)emb;
    for (int i=tid;i<B*(H/4);i+=256){
        int b=i>>8, k4=i&255;
        float4 v = emb4[(size_t)toks[b]*(H/4) + k4];
        v.x=fmaxf(v.x,0.f); v.y=fmaxf(v.y,0.f); v.z=fmaxf(v.z,0.f); v.w=fmaxf(v.w,0.f);
        x4[i]=v;
    }
    __syncthreads();
    int warp=tid>>5, lane=tid&31, rs=lane>>2, ksub=lane&3;
    int g  = warp>>1;                    // gate 0..3 (i,f,g,o)
    int jj = (warp&1)*8 + rs;
    int j0 = blockIdx.x*16;
    int row = g*H + j0 + jj;
    float acc[B];
    gemm_rows<16>(Wih, row, ksub, x4, acc);   // 64 blocks -> deep staging free
#pragma unroll
    for (int i=0;i<4;i++){ int b=ksub*4+i; gs[(g*16+jj)*16+b] = acc[b] + g_gc[row*B+b]; }
    __syncthreads();
    int b=tid&15, j2=tid>>4;
    float iv=gs[(0*16+j2)*16+b], fv=gs[(1*16+j2)*16+b];
    float gv=gs[(2*16+j2)*16+b], ov=gs[(3*16+j2)*16+b];
    int j=j0+j2;
    float c = sigm(fv)*c0[b*H+j] + sigm(iv)*tanhf(gv);
    float h = sigm(ov)*tanhf(c);
    g_h[b*H+j]=h;
}

// -------- persistent per-step fc: 296 blocks pull 64-row tiles from an atomic
// queue (deadlock-free regardless of occupancy; near-perfect wave balance).
// ZIGZAG tile order: odd steps traverse fcW back-to-front so the ~100+MB of
// fcW left resident in the 126MB L2 by the previous step (L2 persists across
// launches; only L1D is flushed) is re-read as hits instead of thrashed.
// h loaded to shared ONCE per block. minBlocks=2 pins the <=128-reg / 2-CTA
// design point. On dup steps degrades to bit-exact copy.
__global__ void __launch_bounds__(256,2) fc_kernel(const float* __restrict__ fcW,
    const float* __restrict__ fcb, float* __restrict__ out, int t){
    extern __shared__ float smem[];
    float4* h4 = (float4*)smem;          // 64KB
    float*  lg = smem + B*H;             // [64][17] padded logits tile
    __shared__ int s_src;
    __shared__ int s_tile;
    int tid = threadIdx.x;
    if (tid==0) s_src=g_src[t];
    __syncthreads();

    if (s_src != t){
        int tp = s_src;
        for(;;){
            if (tid==0) s_tile = atomicAdd(&g_ctr[t],1);
            __syncthreads();
            int tile = s_tile;
            if (tile >= FCB) return;
            for (int i=tid;i<64*B;i+=256){
                int b=i>>6, vl=i&63;
                size_t col = (size_t)tile*64 + vl;
                out[(size_t)b*T*V + (size_t)t*V + col] =
                    out[(size_t)b*T*V + (size_t)tp*V + col];
            }
            __syncthreads();
        }
    }

    const float4* hg = (const float4*)g_h;
    for (int i=tid;i<B*H/4;i+=256) h4[i]=hg[i];
    __syncthreads();
    int warp=tid>>5, lane=tid&31, rs=lane>>2, ksub=lane&3;
    int rowLoc = warp*8 + rs;

    for(;;){
        if (tid==0) s_tile = atomicAdd(&g_ctr[t],1);
        __syncthreads();
        int n = s_tile;
        if (n >= FCB) return;
        int tile = (t & 1) ? (FCB-1-n) : n;   // zigzag across steps for L2 reuse
        int row = tile*64 + rowLoc;
        float acc[B];
        gemm_rows<8>(fcW, row, ksub, h4, acc);
        float bias = fcb[row];
#pragma unroll
        for (int i=0;i<4;i++){ int b=ksub*4+i; lg[rowLoc*17+b] = acc[b]+bias; }
        __syncthreads();
        for (int i=tid;i<64*B;i+=256){
            int b=i>>6, vl=i&63;
            out[(size_t)b*T*V + (size_t)t*V + tile*64 + vl] = lg[vl*17+b];
        }
        // tile-level argmax per batch, first-index tie-break
        int b = tid>>4, r0 = tid&15;
        float bv=-3.4e38f; int bi=0;
        for (int r=r0;r<64;r+=16){ float v=lg[r*17+b]; if (v>bv){bv=v;bi=r;} }
#pragma unroll
        for (int off=8;off;off>>=1){
            float ov=__shfl_xor_sync(0xffffffffu,bv,off,16);
            int   oi=__shfl_xor_sync(0xffffffffu,bi,off,16);
            if (ov>bv || (ov==bv && oi<bi)){bv=ov;bi=oi;}
        }
        if (r0==0){ g_pmax[tile*B+b]=bv; g_pidx[tile*B+b]=tile*64+bi; }
        __syncthreads();                  // lg reused next tile
    }
}

// -------- final in-place log_softmax over each of the 176 rows of length 32000
__global__ void __launch_bounds__(256) lsm_kernel(float* __restrict__ out){
    __shared__ float red[256];
    float* row = out + (size_t)blockIdx.x*V;
    int tid=threadIdx.x;
    float m=-3.4e38f;
    for (int i=tid;i<V;i+=256) m=fmaxf(m,row[i]);
    red[tid]=m; __syncthreads();
    for (int s=128;s;s>>=1){ if (tid<s) red[tid]=fmaxf(red[tid],red[tid+s]); __syncthreads(); }
    m=red[0]; __syncthreads();
    float sum=0.f;
    for (int i=tid;i<V;i+=256) sum+=expf(row[i]-m);
    red[tid]=sum; __syncthreads();
    for (int s=128;s;s>>=1){ if (tid<s) red[tid]+=red[tid+s]; __syncthreads(); }
    float lse=logf(red[0])+m;
    for (int i=tid;i<V;i+=256) row[i]=row[i]-lse;
}

extern "C" void kernel_launch(void* const* d_in, const int* in_sizes, int n_in,
                              void* d_out, int out_size){
    // metadata order: encoder_outputs, h0, c0, emb, W_ih, W_hh, b_ih, b_hh, fc_W, fc_b
    const float* h0 =(const float*)d_in[1];
    const float* c0 =(const float*)d_in[2];
    const float* emb=(const float*)d_in[3];
    const float* Wih=(const float*)d_in[4];
    const float* Whh=(const float*)d_in[5];
    const float* bih=(const float*)d_in[6];
    const float* bhh=(const float*)d_in[7];
    const float* fcW=(const float*)d_in[8];
    const float* fcb=(const float*)d_in[9];
    float* out=(float*)d_out;

    cudaFuncSetAttribute(fc_kernel,     cudaFuncAttributeMaxDynamicSharedMemorySize, (B*H + 64*17)*4);
    cudaFuncSetAttribute(lstm_kernel,   cudaFuncAttributeMaxDynamicSharedMemorySize, (B*H + 4*16*16)*4);
    cudaFuncSetAttribute(gconst_kernel, cudaFuncAttributeMaxDynamicSharedMemorySize, B*H*4);

    gconst_kernel<<<G/64,256,B*H*4>>>(h0,Whh,bih,bhh);
    for (int t=0;t<T;t++){
        lstm_kernel<<<H/16,256,(B*H + 4*16*16)*4>>>(emb,Wih,c0,t);
        fc_kernel<<<FCGRID,256,(B*H + 64*17)*4>>>(fcW,fcb,out,t);
    }
    lsm_kernel<<<B*T,256>>>(out);
}